// round 17
// baseline (speedup 1.0000x reference)
#include <cuda_runtime.h>
#include <cuda_bf16.h>

// MultiBoxLoss (SSD). 2-kernel split:
//  A) stream: per-anchor CE -> g_ce scratch; per-chunk (32 anchors) positive
//     count + (posCE + smoothL1) partials. Coalesced float4 smem staging,
//     front-batched __ldcs on all streamed inputs.
//  B) per-row: k = min(3*npos, nneg); exact k-th largest negative CE via a
//     7-round 32-ary interval search on the float bit pattern (one barrier
//     per round, pre-zeroed per-round counters, redundant per-warp suffix
//     scans); validated (count(>v) < k <= count(>=v)), bisection fallback;
//     top-k sum; last block finalizes the scalar output.

#define ROWS 128
#define AA   8732
#define CC   21
#define CPR  273            // chunks per row: 272 full (32) + 1 partial (28)
#define TOTCH (ROWS * CPR)  // 34944
#define WPB  8              // warps per block in phase A
#define BLKA (TOTCH / WPB)  // 4368
#define NTB  1024
#define PER  9              // ceil(8732/1024)
#define NROUND 7            // 32-ary rounds: wl 31,26,21,16,11,6,1

__device__ float  g_ce[ROWS * AA];      // ce_neg (0 for positives)
__device__ int    g_chunk_pos[TOTCH];
__device__ float  g_chunk_sum[TOTCH];   // posCE + smoothL1 partial per chunk
__device__ double g_sum;
__device__ unsigned long long g_npos;
__device__ unsigned g_done;

// ---------------------------------------------------------------- Phase A
__global__ __launch_bounds__(256) void mbl_phaseA(
    const float* __restrict__ conf,
    const float* __restrict__ loc,
    const int*   __restrict__ lab,
    const float* __restrict__ gloc)
{
    __shared__ float sbuf[WPB * 672];   // 21504 B

    if (blockIdx.x == 0 && threadIdx.x == 0) {
        g_sum = 0.0; g_npos = 0ull; g_done = 0u;
    }

    const int wid  = threadIdx.x >> 5;
    const int lane = threadIdx.x & 31;
    const int chunk = blockIdx.x * WPB + wid;
    const int row = chunk / CPR;
    const int j   = chunk - row * CPR;
    const int na  = (j == CPR - 1) ? (AA - (CPR - 1) * 32) : 32;  // 28 or 32
    const size_t abase = (size_t)row * AA + (size_t)j * 32;
    const size_t idx = abase + (size_t)lane;

    // Issue label load early so it overlaps staging (streaming hint).
    const int lb = (lane < na) ? __ldcs(lab + idx) : 0;

    // Stage this chunk's logits: na*21 floats, contiguous & 16B-aligned.
    float* sw = sbuf + wid * 672;
    const float4* src = (const float4*)(conf + abase * CC);
    const int n4 = (na * CC) >> 2;  // 168 or 147
    float4 q[6];
    #pragma unroll
    for (int i = 0; i < 6; i++) {
        const int t = lane + 32 * i;
        if (t < n4) q[i] = __ldcs(src + t);
    }
    #pragma unroll
    for (int i = 0; i < 6; i++) {
        const int t = lane + 32 * i;
        if (t < n4) ((float4*)sw)[t] = q[i];
    }
    __syncwarp();

    float cev = 0.f;    // ce_neg
    int   isp = 0;
    float psum = 0.f;   // posCE + smoothL1 contribution
    if (lane < na) {
        float v[CC];
        #pragma unroll
        for (int c = 0; c < CC; c++) v[c] = sw[lane * CC + c];

        float m = v[0];
        #pragma unroll
        for (int c = 1; c < CC; c++) m = fmaxf(m, v[c]);
        float s = 0.f;
        #pragma unroll
        for (int c = 0; c < CC; c++) s += __expf(v[c] - m);

        const float ce = m + __logf(s) - v[lb];

        if (lb > 0) {
            isp = 1;
            psum = ce;
            const float4 l4 = __ldcs((const float4*)loc  + idx);
            const float4 g4 = __ldcs((const float4*)gloc + idx);
            float d, ad;
            d = l4.x - g4.x; ad = fabsf(d); psum += (ad < 1.f) ? 0.5f * d * d : ad - 0.5f;
            d = l4.y - g4.y; ad = fabsf(d); psum += (ad < 1.f) ? 0.5f * d * d : ad - 0.5f;
            d = l4.z - g4.z; ad = fabsf(d); psum += (ad < 1.f) ? 0.5f * d * d : ad - 0.5f;
            d = l4.w - g4.w; ad = fabsf(d); psum += (ad < 1.f) ? 0.5f * d * d : ad - 0.5f;
        } else {
            cev = ce;   // strictly > 0 for finite logits
        }
        g_ce[idx] = cev;
    }

    // Warp-level chunk partials
    int pc = (int)__reduce_add_sync(0xFFFFFFFFu, (unsigned)isp);
    #pragma unroll
    for (int off = 16; off; off >>= 1)
        psum += __shfl_xor_sync(0xFFFFFFFFu, psum, off);
    if (lane == 0) {
        g_chunk_pos[chunk] = pc;
        g_chunk_sum[chunk] = psum;
    }
}

// ---------------------------------------------------------------- Phase B
// Warp-aggregated smem histogram add (lanes in 'mask' with equal bin elect
// one leader that adds popc once).
__device__ __forceinline__ void hist_add(unsigned* h, unsigned bin, unsigned mask)
{
    const unsigned peers  = __match_any_sync(mask, bin);
    const unsigned leader = __ffs(peers) - 1u;
    if ((threadIdx.x & 31u) == leader)
        atomicAdd(&h[bin], __popc(peers));
}

__global__ __launch_bounds__(NTB) void mbl_phaseB(float* __restrict__ out)
{
    const int b    = blockIdx.x;
    const int tid  = threadIdx.x;
    const int wid  = tid >> 5;
    const unsigned lane = tid & 31u;

    __shared__ unsigned s_cnt[NROUND * 32];   // per-round 32-ary counters
    __shared__ unsigned s_fb[32];             // bisection-fallback counters
    __shared__ float    s_wf[32];             // per-warp float slots
    __shared__ int      s_wi[32];             // per-warp int slots
    __shared__ unsigned s_wu[32];             // per-warp unsigned slots
    __shared__ unsigned s_wu2[32];            // per-warp unsigned slots

    // Front-issue this row's ce_neg loads to overlap everything below.
    float ce[PER];
    #pragma unroll
    for (int i = 0; i < PER; i++) {
        const int a = tid + i * NTB;
        ce[i] = (a < AA) ? __ldg(&g_ce[(size_t)b * AA + a]) : 0.f;
    }

    // Per-warp partial reduction of this row's chunk partials (no atomics).
    {
        int   pc = 0;
        float ps = 0.f;
        if (tid < CPR) {
            pc = g_chunk_pos[b * CPR + tid];
            ps = g_chunk_sum[b * CPR + tid];
        }
        pc = (int)__reduce_add_sync(0xFFFFFFFFu, (unsigned)pc);
        #pragma unroll
        for (int off = 16; off; off >>= 1)
            ps += __shfl_down_sync(0xFFFFFFFFu, ps, off);
        if (lane == 0) { s_wi[wid] = pc; s_wf[wid] = ps; }
    }

    unsigned bits[PER];
    #pragma unroll
    for (int i = 0; i < PER; i++) bits[i] = __float_as_uint(ce[i]);

    // Zero all per-round counters + fallback counters once.
    if (tid < NROUND * 32) s_cnt[tid] = 0u;
    if (tid < 32) s_fb[tid] = 0u;
    __syncthreads();   // slots + zeroed counters visible

    // Every warp redundantly folds the per-warp partial slots (no publish bar).
    int   npos;
    float psum;
    {
        int   p = s_wi[lane];
        float f = s_wf[lane];
        p = (int)__reduce_add_sync(0xFFFFFFFFu, (unsigned)p);
        #pragma unroll
        for (int off = 16; off; off >>= 1)
            f += __shfl_down_sync(0xFFFFFFFFu, f, off);
        npos = __shfl_sync(0xFFFFFFFFu, p, 0);
        psum = __shfl_sync(0xFFFFFFFFu, f, 0);
    }
    const int k = min(3 * npos, AA - npos);   // uniform across block

    double negsum = 0.0;
    if (k > 0) {
        // ---- 32-ary interval search: 7 rounds, exact k-th largest bits ----
        unsigned lo = 0u;   // interval [lo, lo + 2^wl)
        int      wl = 31;   // all ce_neg bit patterns < 2^31
        unsigned r  = (unsigned)k;

        #pragma unroll
        for (int rd = 0; rd < NROUND; rd++) {
            unsigned* cnt = &s_cnt[rd * 32];
            const int shift = (wl > 5) ? (wl - 5) : 0;
            const unsigned nb = 1u << (wl - shift);   // <= 32 buckets

            #pragma unroll
            for (int i = 0; i < PER; i++) {
                const unsigned bk = (bits[i] - lo) >> shift;  // wraps out if < lo
                const bool act = (bk < nb);
                const unsigned mask = __ballot_sync(0xFFFFFFFFu, act);
                if (act) hist_add(cnt, bk, mask);
            }
            __syncthreads();

            // Redundant per-warp suffix scan of the (<=32) counters.
            const unsigned corig = cnt[31u - lane];   // bucket 31-lane (0 if >= nb)
            unsigned cum = corig;
            #pragma unroll
            for (int off = 1; off < 32; off <<= 1) {
                const unsigned x = __shfl_up_sync(0xFFFFFFFFu, cum, off);
                if (lane >= off) cum += x;
            }
            // lane L holds cumTop(31-L); find highest bucket with cumTop >= r.
            const unsigned ball = __ballot_sync(0xFFFFFFFFu, cum >= r);
            const int L = __ffs((int)ball) - 1;
            const unsigned cumL = __shfl_sync(0xFFFFFFFFu, cum,   L);
            const unsigned cL   = __shfl_sync(0xFFFFFFFFu, corig, L);
            const unsigned beta = 31u - (unsigned)L;
            r  = r - (cumL - cL);           // rank within bucket beta
            lo = lo + (beta << shift);
            wl = shift;
            // no barrier needed: next round uses a fresh pre-zeroed counter row
        }
        unsigned vbits = lo;

        // ---- Exact validation: count(>v) < k <= count(>=v) ----
        {
            unsigned cgt = 0u, cge = 0u;
            #pragma unroll
            for (int i = 0; i < PER; i++) {
                cgt += (bits[i] >  vbits) ? 1u : 0u;
                cge += (bits[i] >= vbits) ? 1u : 0u;
            }
            cgt = __reduce_add_sync(0xFFFFFFFFu, cgt);
            cge = __reduce_add_sync(0xFFFFFFFFu, cge);
            if (lane == 0) { s_wu[wid] = cgt; s_wu2[wid] = cge; }
        }
        __syncthreads();
        unsigned vgt, vge;
        {
            const unsigned a = __reduce_add_sync(0xFFFFFFFFu, s_wu[lane]);
            const unsigned e = __reduce_add_sync(0xFFFFFFFFu, s_wu2[lane]);
            vgt = __shfl_sync(0xFFFFFFFFu, a, 0);
            vge = __shfl_sync(0xFFFFFFFFu, e, 0);
        }
        const bool valid = (vgt < (unsigned)k) && (vge >= (unsigned)k);

        if (!valid) {
            // ---- Fallback: bisection on float bits (known-correct) ----
            unsigned lo2 = 0u, hi2 = 0x7F800000u;
            int iter = 0;
            while (lo2 < hi2) {
                const unsigned mid = (lo2 + hi2) >> 1;
                unsigned c = 0;
                #pragma unroll
                for (int i = 0; i < PER; i++) c += (bits[i] > mid) ? 1u : 0u;
                c = __reduce_add_sync(0xFFFFFFFFu, c);
                if (lane == 0) atomicAdd(&s_fb[iter], c);
                __syncthreads();
                const unsigned tot = s_fb[iter];
                if (tot < (unsigned)k) hi2 = mid; else lo2 = mid + 1u;
                iter++;
            }
            vbits = lo2;
        }

        const float vth = __uint_as_float(vbits);

        // Sum of values strictly greater + tie fill (per-warp slots).
        float    fs  = 0.f;
        unsigned cgt = 0u;
        #pragma unroll
        for (int i = 0; i < PER; i++)
            if (bits[i] > vbits) { fs += ce[i]; cgt++; }
        cgt = __reduce_add_sync(0xFFFFFFFFu, cgt);
        #pragma unroll
        for (int off = 16; off; off >>= 1)
            fs += __shfl_down_sync(0xFFFFFFFFu, fs, off);
        if (lane == 0) { s_wf[wid] = fs; s_wu[wid] = cgt; }
        __syncthreads();
        {
            const unsigned c = __reduce_add_sync(0xFFFFFFFFu, s_wu[lane]);
            float f = s_wf[lane];
            #pragma unroll
            for (int off = 16; off; off >>= 1)
                f += __shfl_down_sync(0xFFFFFFFFu, f, off);
            const unsigned ctot = __shfl_sync(0xFFFFFFFFu, c, 0);
            const float    ftot = __shfl_sync(0xFFFFFFFFu, f, 0);
            negsum = (double)ftot + (double)(k - (int)ctot) * (double)vth;
        }
    }

    if (tid == 0) {
        atomicAdd(&g_sum, (double)psum + negsum);
        atomicAdd(&g_npos, (unsigned long long)npos);
        __threadfence();
        const unsigned done = atomicAdd(&g_done, 1u);
        if (done == ROWS - 1) {
            __threadfence();
            const double ts = atomicAdd(&g_sum, 0.0);
            const unsigned long long tp = atomicAdd(&g_npos, 0ull);
            out[0] = (float)(ts / (double)tp);
        }
    }
}

extern "C" void kernel_launch(void* const* d_in, const int* in_sizes, int n_in,
                              void* d_out, int out_size)
{
    const float* conf = (const float*)d_in[0];
    const float* loc  = (const float*)d_in[1];
    const int*   lab  = (const int*)  d_in[2];
    const float* gloc = (const float*)d_in[3];
    float* out = (float*)d_out;

    mbl_phaseA<<<BLKA, 256>>>(conf, loc, lab, gloc);
    mbl_phaseB<<<ROWS, NTB>>>(out);
}